// round 1
// baseline (speedup 1.0000x reference)
#include <cuda_runtime.h>
#include <math.h>
#include <stdint.h>

// Problem constants
#define Tt 1024
#define Cc 2048
#define Hh 32
#define Nn 64
#define TC (Tt*Cc)          // 2097152

// ---------------- packed f32x2 helpers ----------------
__device__ __forceinline__ unsigned long long f2pack(float x, float y){
  unsigned long long r;
  asm("mov.b64 %0, {%1, %2};" : "=l"(r) : "r"(__float_as_uint(x)), "r"(__float_as_uint(y)));
  return r;
}
__device__ __forceinline__ float2 f2unpack(unsigned long long p){
  unsigned int lo, hi;
  asm("mov.b64 {%0, %1}, %2;" : "=r"(lo), "=r"(hi) : "l"(p));
  return make_float2(__uint_as_float(lo), __uint_as_float(hi));
}
__device__ __forceinline__ unsigned long long fma2(unsigned long long a, unsigned long long b, unsigned long long c){
  unsigned long long d;
  asm("fma.rn.f32x2 %0, %1, %2, %3;" : "=l"(d) : "l"(a), "l"(b), "l"(c));
  return d;
}
__device__ __forceinline__ unsigned long long mul2(unsigned long long a, unsigned long long b){
  unsigned long long d;
  asm("mul.rn.f32x2 %0, %1, %2;" : "=l"(d) : "l"(a), "l"(b));
  return d;
}

// ---------------- scratch (device globals; no allocations allowed) ----------------
// layout (floats):
//  bcat   : 2048*256              = 524288
//  part   : 8*1024*256            = 2097152
//  hcat   : 1024*256              = 262144
//  gw,ga,gv,r,k,v,dec,asc,bsc,ksc,vsc,o : 12 * TC
#define SCRATCH_FLOATS (524288 + 2097152 + 262144 + 12*TC)
__device__ float g_scratch[SCRATCH_FLOATS];

// ---------------- generic fp32 GEMM core (128x128x16, 8x8/thread, f32x2) ----------------
__device__ __forceinline__ void gemm_core(
    const float* __restrict__ A, int lda,
    const float* __restrict__ B, float* __restrict__ C, int N,
    int kbegin, int kend, int m0, int n0,
    float (*As)[128], float (*Bs)[128])
{
  int tid = threadIdx.x;                 // 256 threads
  int tm = (tid >> 4) << 3;
  int tn = (tid & 15) << 3;
  unsigned long long acc[8][4];
  #pragma unroll
  for (int i=0;i<8;i++)
    #pragma unroll
    for (int q=0;q<4;q++) acc[i][q] = 0ull;

  for (int k0 = kbegin; k0 < kend; k0 += 16) {
    #pragma unroll
    for (int i=0;i<8;i++){
      int e = tid + i*256;
      int row = e >> 4, col = e & 15;
      As[col][row] = A[(size_t)(m0+row)*lda + k0 + col];
    }
    #pragma unroll
    for (int i=0;i<8;i++){
      int e = tid + i*256;
      int row = e >> 7, col = e & 127;
      int n = n0 + col;
      Bs[row][col] = (n < N) ? B[(size_t)(k0+row)*N + n] : 0.f;
    }
    __syncthreads();
    #pragma unroll
    for (int kk=0;kk<16;kk++){
      float4 a0 = *(const float4*)&As[kk][tm];
      float4 a1 = *(const float4*)&As[kk][tm+4];
      ulonglong2 b0 = *(const ulonglong2*)&Bs[kk][tn];
      ulonglong2 b1 = *(const ulonglong2*)&Bs[kk][tn+4];
      unsigned long long bp0 = b0.x, bp1 = b0.y, bp2 = b1.x, bp3 = b1.y;
      float av[8] = {a0.x,a0.y,a0.z,a0.w,a1.x,a1.y,a1.z,a1.w};
      #pragma unroll
      for (int i=0;i<8;i++){
        unsigned long long ap = f2pack(av[i], av[i]);
        acc[i][0] = fma2(ap, bp0, acc[i][0]);
        acc[i][1] = fma2(ap, bp1, acc[i][1]);
        acc[i][2] = fma2(ap, bp2, acc[i][2]);
        acc[i][3] = fma2(ap, bp3, acc[i][3]);
      }
    }
    __syncthreads();
  }
  #pragma unroll
  for (int i=0;i<8;i++){
    int m = m0 + tm + i;
    #pragma unroll
    for (int q=0;q<4;q++){
      float2 v2 = f2unpack(acc[i][q]);
      int n = n0 + tn + 2*q;
      if (n   < N) C[(size_t)m*N + n    ] = v2.x;
      if (n+1 < N) C[(size_t)m*N + n + 1] = v2.y;
    }
  }
}

// z-dim selects one of up to 3 (B, C) pairs
__global__ void __launch_bounds__(256) sgemm3(
    const float* __restrict__ A, int lda,
    const float* B0, const float* B1, const float* B2,
    float* C0, float* C1, float* C2,
    int M, int N, int K)
{
  __shared__ float As[16][128];
  __shared__ float Bs[16][128];
  const float* B = (blockIdx.z == 0) ? B0 : (blockIdx.z == 1) ? B1 : B2;
  float*       C = (blockIdx.z == 0) ? C0 : (blockIdx.z == 1) ? C1 : C2;
  gemm_core(A, lda, B, C, N, 0, K, blockIdx.y*128, blockIdx.x*128, As, Bs);
}

// split-K: z = slice index, writes partials (deterministic, no atomics)
__global__ void __launch_bounds__(256) sgemm_splitk(
    const float* __restrict__ A, int lda,
    const float* __restrict__ B, float* __restrict__ Cpart,
    int M, int N, int Kslice)
{
  __shared__ float As[16][128];
  __shared__ float Bs[16][128];
  int kb = blockIdx.z * Kslice;
  gemm_core(A, lda, B, Cpart + (size_t)blockIdx.z*M*N, N,
            kb, kb + Kslice, blockIdx.y*128, blockIdx.x*128, As, Bs);
}

// ---------------- small kernels ----------------
__global__ void build_bcat(const float* __restrict__ w1, const float* __restrict__ a1,
                           const float* __restrict__ v1, float* __restrict__ bcat)
{
  int i = blockIdx.x*256 + threadIdx.x;    // 2048*256
  if (i >= 2048*256) return;
  int row = i >> 8, col = i & 255;
  float val;
  if      (col <  96) val = w1[row*96 + col];
  else if (col < 192) val = a1[row*96 + col - 96];
  else                val = v1[row*64 + col - 192];
  bcat[i] = val;
}

__global__ void reduce_hcat(const float* __restrict__ part, float* __restrict__ hcat)
{
  int i = blockIdx.x*256 + threadIdx.x;    // 1024*256
  if (i >= 1024*256) return;
  float s = 0.f;
  #pragma unroll
  for (int z = 0; z < 8; z++) s += part[(size_t)z*1024*256 + i];
  int col = i & 255;
  if (col < 96) s = tanhf(s);              // tanh only on the w-path
  hcat[i] = s;
}

__device__ __forceinline__ float sigmoidf_(float x){ return 1.f/(1.f + expf(-x)); }

// per (t, head) block of 64 threads: all elementwise prep + kk L2-norm
__global__ void __launch_bounds__(64) prep_kernel(
    float* __restrict__ k, float* __restrict__ v,
    const float* __restrict__ gw, const float* __restrict__ ga, const float* __restrict__ gv,
    const float* __restrict__ v_first, const float* __restrict__ mask,
    const float* __restrict__ w0, const float* __restrict__ a0, const float* __restrict__ v0,
    const float* __restrict__ k_k, const float* __restrict__ k_a,
    float* __restrict__ dec, float* __restrict__ asc, float* __restrict__ bsc,
    float* __restrict__ ksc, float* __restrict__ vsc)
{
  int t = blockIdx.x >> 5;
  int h = blockIdx.x & 31;
  int tid = threadIdx.x;
  int c = (h << 6) | tid;
  int idx = t*Cc + c;

  float kr  = k[idx];
  float kkv = kr * k_k[c];

  __shared__ float red[64];
  red[tid] = kkv*kkv;
  __syncthreads();
  #pragma unroll
  for (int s = 32; s > 0; s >>= 1){
    if (tid < s) red[tid] += red[tid + s];
    __syncthreads();
  }
  float kkn = kkv / fmaxf(sqrtf(red[0]), 1e-12f);

  float av = sigmoidf_(a0[c] + ga[idx]);
  float m  = mask[t];

  // w = -softplus(-(w0 + gw)) - 0.6 ; dec = exp(-exp(w))
  float y  = w0[c] + gw[idx];
  float z  = -y;
  float sp = (z > 20.f) ? z : log1pf(expf(z));
  float w  = -sp - 0.6f;
  float d  = expf(-expf(w));
  d = d*m + (1.f - m);

  float vr = v[idx];
  float sv = sigmoidf_(v0[c] + gv[idx]);
  float vm = fmaf(v_first[idx] - vr, sv, vr);

  float ku = kr * fmaf(av - 1.f, k_a[c], 1.f);

  k[idx]   = ku;          // updated k (for residual)
  v[idx]   = vm;          // mixed v (for residual)
  dec[idx] = d;
  ksc[idx] = ku * m;
  vsc[idx] = vm * m;
  asc[idx] = -kkn * m;
  bsc[idx] = kkn * av * m;
}

// sequential RWKV-7 scan: one block per head, thread i owns state row i (packed f32x2)
__global__ void __launch_bounds__(64) scan_kernel(
    const float* __restrict__ dec, const float* __restrict__ r,
    const float* __restrict__ kq, const float* __restrict__ vq,
    const float* __restrict__ aq, const float* __restrict__ bq,
    float* __restrict__ o)
{
  int h = blockIdx.x;
  int tid = threadIdx.x;
  __shared__ float sb[2][6][64];
  unsigned long long S[32];
  #pragma unroll
  for (int j=0;j<32;j++) S[j] = 0ull;

  int base = (h << 6) + tid;
  float pre[6];
  pre[0]=dec[base]; pre[1]=r[base]; pre[2]=kq[base];
  pre[3]=vq[base];  pre[4]=aq[base]; pre[5]=bq[base];

  for (int t = 0; t < Tt; t++){
    int p = t & 1;
    sb[p][0][tid]=pre[0]; sb[p][1][tid]=pre[1]; sb[p][2][tid]=pre[2];
    sb[p][3][tid]=pre[3]; sb[p][4][tid]=pre[4]; sb[p][5][tid]=pre[5];
    __syncthreads();
    if (t < Tt-1){
      int nb = (t+1)*Cc + base;
      pre[0]=dec[nb]; pre[1]=r[nb]; pre[2]=kq[nb];
      pre[3]=vq[nb];  pre[4]=aq[nb]; pre[5]=bq[nb];
    }
    const unsigned long long* dd = (const unsigned long long*)sb[p][0];
    const unsigned long long* rr = (const unsigned long long*)sb[p][1];
    const unsigned long long* kk = (const unsigned long long*)sb[p][2];
    const unsigned long long* aa = (const unsigned long long*)sb[p][4];
    const unsigned long long* bb = (const unsigned long long*)sb[p][5];

    // sa_i = sum_j S[i][j] * a[j]
    unsigned long long acc0 = 0ull, acc1 = 0ull;
    #pragma unroll
    for (int j=0;j<32;j+=2){
      acc0 = fma2(S[j],   aa[j],   acc0);
      acc1 = fma2(S[j+1], aa[j+1], acc1);
    }
    float2 u0 = f2unpack(acc0), u1 = f2unpack(acc1);
    float sa = (u0.x + u0.y) + (u1.x + u1.y);

    float vi = sb[p][3][tid];
    unsigned long long sa2 = f2pack(sa, sa);
    unsigned long long vi2 = f2pack(vi, vi);

    // S = S*dec + sa*b + v_i*k ;  out_i = sum_j S[i][j]*r[j]
    unsigned long long oa0 = 0ull, oa1 = 0ull;
    #pragma unroll
    for (int j=0;j<32;j+=2){
      S[j]   = fma2(S[j],   dd[j],   fma2(sa2, bb[j],   mul2(vi2, kk[j])));
      oa0    = fma2(S[j],   rr[j],   oa0);
      S[j+1] = fma2(S[j+1], dd[j+1], fma2(sa2, bb[j+1], mul2(vi2, kk[j+1])));
      oa1    = fma2(S[j+1], rr[j+1], oa1);
    }
    float2 w0_ = f2unpack(oa0), w1_ = f2unpack(oa1);
    o[t*Cc + base] = (w0_.x + w0_.y) + (w1_.x + w1_.y);
  }
}

// residual: o += (sum_n r*k*r_k)[t,h] * v
__global__ void __launch_bounds__(64) post_kernel(
    const float* __restrict__ r, const float* __restrict__ k,
    const float* __restrict__ v, const float* __restrict__ r_k,
    float* __restrict__ o)
{
  int t = blockIdx.x >> 5;
  int h = blockIdx.x & 31;
  int tid = threadIdx.x;
  int c = (h << 6) | tid;
  int idx = t*Cc + c;
  __shared__ float red[64];
  red[tid] = r[idx]*k[idx]*r_k[c];
  __syncthreads();
  #pragma unroll
  for (int s = 32; s > 0; s >>= 1){
    if (tid < s) red[tid] += red[tid + s];
    __syncthreads();
  }
  o[idx] += red[0]*v[idx];
}

__global__ void copy_vfirst(const float* __restrict__ vf, float* __restrict__ out)
{
  int i = blockIdx.x*256 + threadIdx.x;
  if (i < TC) out[i] = vf[i];
}

// ---------------- host launcher ----------------
extern "C" void kernel_launch(void* const* d_in, const int* in_sizes, int n_in,
                              void* d_out, int out_size)
{
  const float* x        = (const float*)d_in[0];
  const float* v_first  = (const float*)d_in[1];
  const float* mask     = (const float*)d_in[2];
  const float* w0       = (const float*)d_in[3];
  const float* w1       = (const float*)d_in[4];
  const float* w2       = (const float*)d_in[5];
  const float* a0       = (const float*)d_in[6];
  const float* a1       = (const float*)d_in[7];
  const float* a2       = (const float*)d_in[8];
  const float* v0       = (const float*)d_in[9];
  const float* v1       = (const float*)d_in[10];
  const float* v2       = (const float*)d_in[11];
  const float* k_k      = (const float*)d_in[12];
  const float* k_a      = (const float*)d_in[13];
  const float* r_k      = (const float*)d_in[14];
  const float* Wr       = (const float*)d_in[15];
  const float* Wk       = (const float*)d_in[16];
  const float* Wv       = (const float*)d_in[17];
  const float* Wo       = (const float*)d_in[18];
  float* outf = (float*)d_out;

  float* S = nullptr;
  cudaGetSymbolAddress((void**)&S, g_scratch);

  float* bcat = S;
  float* part = bcat + 524288;
  float* hcat = part + 2097152;
  float* gw   = hcat + 262144;
  float* ga   = gw  + TC;
  float* gv   = ga  + TC;
  float* r    = gv  + TC;
  float* k    = r   + TC;
  float* v    = k   + TC;
  float* dec  = v   + TC;
  float* asc  = dec + TC;
  float* bsc  = asc + TC;
  float* ksc  = bsc + TC;
  float* vsc  = ksc + TC;
  float* o    = vsc + TC;

  // 1) concat thin weights: bcat = [w1 | a1 | v1]  (2048 x 256)
  build_bcat<<<2048, 256>>>(w1, a1, v1, bcat);

  // 2) hcat_pre = x @ bcat via split-K(8)  -> partials
  {
    dim3 grid(2, 8, 8);
    sgemm_splitk<<<grid, 256>>>(x, Cc, bcat, part, 1024, 256, 256);
  }
  // 3) reduce partials (+ tanh on w-path cols 0..95)
  reduce_hcat<<<1024, 256>>>(part, hcat);

  // 4) mid GEMMs: gw = tanh(x@w1) @ w2 ; ga = (x@a1)@a2 ; gv = (x@v1)@v2
  {
    dim3 grid(16, 8, 1);
    sgemm3<<<grid, 256>>>(hcat,       256, w2, w2, w2, gw, gw, gw, 1024, Cc, 96);
    sgemm3<<<grid, 256>>>(hcat + 96,  256, a2, a2, a2, ga, ga, ga, 1024, Cc, 96);
    sgemm3<<<grid, 256>>>(hcat + 192, 256, v2, v2, v2, gv, gv, gv, 1024, Cc, 64);
  }

  // 5) big GEMMs: r,k,v = x @ {Wr,Wk,Wv}  (fused over grid.z)
  {
    dim3 grid(16, 8, 3);
    sgemm3<<<grid, 256>>>(x, Cc, Wr, Wk, Wv, r, k, v, 1024, Cc, Cc);
  }

  // 6) elementwise prep (+ per-head kk norm, masking, decay)
  prep_kernel<<<Tt*Hh, 64>>>(k, v, gw, ga, gv, v_first, mask,
                             w0, a0, v0, k_k, k_a,
                             dec, asc, bsc, ksc, vsc);

  // 7) sequential scan (one block per head)
  scan_kernel<<<Hh, 64>>>(dec, r, ksc, vsc, asc, bsc, o);

  // 8) residual
  post_kernel<<<Tt*Hh, 64>>>(r, k, v, r_k, o);

  // 9) final GEMM: out = o @ Wo
  {
    dim3 grid(16, 8, 1);
    sgemm3<<<grid, 256>>>(o, Cc, Wo, Wo, Wo, outf, outf, outf, 1024, Cc, Cc);
  }

  // 10) second tuple element: v_first pass-through
  if (out_size >= 2*TC) {
    copy_vfirst<<<(TC + 255)/256, 256>>>(v_first, outf + TC);
  }
}

// round 5
// speedup vs baseline: 1.5472x; 1.5472x over previous
#include <cuda_runtime.h>
#include <cuda_bf16.h>
#include <math.h>
#include <stdint.h>

// Problem constants
#define Tt 1024
#define Cc 2048
#define Hh 32
#define Nn 64
#define TC (Tt*Cc)          // 2097152

// tcgen05 available only in architecture-specific compilation passes
#if defined(__CUDA_ARCH_FEAT_SM103_ALL) || defined(__CUDA_ARCH_FEAT_SM100_ALL) || defined(__CUDA_ARCH_SPECIFIC__)
#define HAS_TCGEN05 1
#else
#define HAS_TCGEN05 0
#endif

// ---------------- packed f32x2 helpers ----------------
__device__ __forceinline__ unsigned long long f2pack(float x, float y){
  unsigned long long r;
  asm("mov.b64 %0, {%1, %2};" : "=l"(r) : "r"(__float_as_uint(x)), "r"(__float_as_uint(y)));
  return r;
}
__device__ __forceinline__ float2 f2unpack(unsigned long long p){
  unsigned int lo, hi;
  asm("mov.b64 {%0, %1}, %2;" : "=r"(lo), "=r"(hi) : "l"(p));
  return make_float2(__uint_as_float(lo), __uint_as_float(hi));
}
__device__ __forceinline__ unsigned long long fma2(unsigned long long a, unsigned long long b, unsigned long long c){
  unsigned long long d;
  asm("fma.rn.f32x2 %0, %1, %2, %3;" : "=l"(d) : "l"(a), "l"(b), "l"(c));
  return d;
}
__device__ __forceinline__ unsigned long long mul2(unsigned long long a, unsigned long long b){
  unsigned long long d;
  asm("mul.rn.f32x2 %0, %1, %2;" : "=l"(d) : "l"(a), "l"(b));
  return d;
}

// ---------------- tcgen05 / mbarrier helpers (sm_103a) ----------------
__device__ __forceinline__ uint32_t smem_u32(const void* p){
  uint32_t a;
  asm("{ .reg .u64 t; cvta.to.shared.u64 t, %1; cvt.u32.u64 %0, t; }" : "=r"(a) : "l"(p));
  return a;
}

#define SW128(x) ((x) ^ (((x) >> 3) & 0x70))

#if HAS_TCGEN05
__device__ __forceinline__ uint32_t elect1(){
  uint32_t r;
  asm volatile("{\n\t.reg .pred p;\n\telect.sync _|p, 0xFFFFFFFF;\n\tselp.b32 %0, 1, 0, p;\n\t}" : "=r"(r));
  return r;
}

#define T5_ALLOC(sa, n)   asm volatile("tcgen05.alloc.cta_group::1.sync.aligned.shared::cta.b32 [%0], %1;" :: "r"(sa), "r"(n) : "memory")
#define T5_DEALLOC(t, n)  asm volatile("tcgen05.dealloc.cta_group::1.sync.aligned.b32 %0, %1;" :: "r"(t), "r"(n))
#define T5_RELINQ()       asm volatile("tcgen05.relinquish_alloc_permit.cta_group::1.sync.aligned;")
#define T5_COMMIT(mb)     asm volatile("tcgen05.commit.cta_group::1.mbarrier::arrive::one.shared::cluster.b64 [%0];" :: "r"(mb) : "memory")
#define T5_FENCE_AFTER()  asm volatile("tcgen05.fence::after_thread_sync;" ::: "memory")
#define T5_WAIT_LD()      asm volatile("tcgen05.wait::ld.sync.aligned;" ::: "memory")
#define FENCE_ASYNC()     asm volatile("fence.proxy.async.shared::cta;" ::: "memory")

#define MBAR_INIT(mb, cnt) asm volatile("mbarrier.init.shared.b64 [%0], %1;" :: "r"(mb), "r"(cnt) : "memory")
#define MBAR_INVAL(mb)     asm volatile("mbarrier.inval.shared.b64 [%0];" :: "r"(mb) : "memory")

#define MBAR_WAIT(mb, ph) do { \
  uint32_t _m = (mb), _p = (ph), _d; \
  asm volatile("{\n\t.reg .pred p;\n\tmbarrier.try_wait.parity.acquire.cta.shared::cta.b64 p, [%1], %2;\n\tselp.b32 %0, 1, 0, p;\n\t}" \
               : "=r"(_d) : "r"(_m), "r"(_p) : "memory"); \
  while (!_d) { \
    asm volatile("{\n\t.reg .pred p;\n\tmbarrier.try_wait.parity.acquire.cta.shared::cta.b64 p, [%1], %2, 0x989680;\n\tselp.b32 %0, 1, 0, p;\n\t}" \
                 : "=r"(_d) : "r"(_m), "r"(_p) : "memory"); \
  } } while(0)

#define LDTM_X32(r, ta) \
    asm volatile( \
        "tcgen05.ld.sync.aligned.32x32b.x32.b32 " \
        "{%0, %1, %2, %3, %4, %5, %6, %7, " \
        " %8, %9, %10, %11, %12, %13, %14, %15, " \
        " %16, %17, %18, %19, %20, %21, %22, %23, " \
        " %24, %25, %26, %27, %28, %29, %30, %31}, [%32];" \
        : "=r"((r)[0]),  "=r"((r)[1]),  "=r"((r)[2]),  "=r"((r)[3]), \
          "=r"((r)[4]),  "=r"((r)[5]),  "=r"((r)[6]),  "=r"((r)[7]), \
          "=r"((r)[8]),  "=r"((r)[9]),  "=r"((r)[10]), "=r"((r)[11]), \
          "=r"((r)[12]), "=r"((r)[13]), "=r"((r)[14]), "=r"((r)[15]), \
          "=r"((r)[16]), "=r"((r)[17]), "=r"((r)[18]), "=r"((r)[19]), \
          "=r"((r)[20]), "=r"((r)[21]), "=r"((r)[22]), "=r"((r)[23]), \
          "=r"((r)[24]), "=r"((r)[25]), "=r"((r)[26]), "=r"((r)[27]), \
          "=r"((r)[28]), "=r"((r)[29]), "=r"((r)[30]), "=r"((r)[31]) \
        : "r"(ta))

__device__ __forceinline__ uint64_t sdesc(uint32_t addr){
  const uint64_t base = (2ull << 61) | (1ull << 46) | (64ull << 32) | (1ull << 16);
  return base | ((uint64_t)(addr >> 4) & 0x3FFF);
}

__device__ __forceinline__ void mma_ss_f16(uint32_t d, uint64_t ad, uint64_t bd, uint32_t idesc, uint32_t en){
  asm volatile(
    "{\n\t.reg .pred p;\n\tsetp.ne.u32 p, %5, 0;\n\t"
    "tcgen05.mma.cta_group::1.kind::f16 [%0], %1, %2, %3, {%4, %4, %4, %4}, p;\n\t}"
    :: "r"(d), "l"(ad), "l"(bd), "r"(idesc), "r"(0u), "r"(en) : "memory");
}

// idesc: dtype F32, atype/btype BF16, N=64, M=128 (proven atom geometry)
#define IDESC_128x64 ((1u<<4) | (1u<<7) | (1u<<10) | ((64u/8u)<<17) | ((128u/16u)<<24))
#endif // HAS_TCGEN05

// ---------------- scratch (device globals; no allocations allowed) ----------------
#define SCRATCH_FLOATS (524288 + 2097152 + 262144 + 12*TC)
__device__ float g_scratch[SCRATCH_FLOATS];

// bf16 scratch: xh,xl (TC each), oh,ol (TC each), 4 weights x (hi+lo) x 4M
#define WSZ (2048*2048)
__device__ __align__(16) __nv_bfloat16 g_bf16[4*TC + 8*WSZ];

// ---------------- tcgen05 split-bf16 GEMM (C = A @ W, A fp32-split, W^T-split) --------
// One CTA = 128x128 C tile; K chunks of 64 bf16. Single-buffer serialized chunk loop.
// Requested smem oversized to force 1 CTA/SM (removes cross-CTA TMEM interaction).
#define GEMM_CHUNKS 32
#define GEMM_SMEM_USED (1024 + 65536)
#define GEMM_SMEM_ALLOC 163840

__device__ __forceinline__ void load_tile16(char* dst, const __nv_bfloat16* __restrict__ g,
                                            int row0, int k0, int tid){
  #pragma unroll
  for (int i = 0; i < 8; i++){
    int e = tid + (i << 7);
    int row = e >> 3, seg = e & 7;
    uint4 v = *(const uint4*)(g + (size_t)(row0 + row)*2048 + k0 + (seg << 3));
    *(uint4*)(dst + SW128(row*128 + seg*16)) = v;
  }
}

__global__ void __launch_bounds__(128)
#if HAS_TCGEN05
__cluster_dims__(1, 1, 1)
#endif
gemm_tc(
    const __nv_bfloat16* __restrict__ Ah, const __nv_bfloat16* __restrict__ Al,
    const __nv_bfloat16* __restrict__ Bh0, const __nv_bfloat16* __restrict__ Bl0,
    const __nv_bfloat16* __restrict__ Bh1, const __nv_bfloat16* __restrict__ Bl1,
    const __nv_bfloat16* __restrict__ Bh2, const __nv_bfloat16* __restrict__ Bl2,
    float* C0, float* C1, float* C2)
{
  extern __shared__ __align__(1024) char smem[];
  int tid = threadIdx.x;
  int m0 = blockIdx.y * 128, n0 = blockIdx.x * 128;
  const __nv_bfloat16* Bh = (blockIdx.z == 0) ? Bh0 : (blockIdx.z == 1) ? Bh1 : Bh2;
  const __nv_bfloat16* Bl = (blockIdx.z == 0) ? Bl0 : (blockIdx.z == 1) ? Bl1 : Bl2;
  float* C               = (blockIdx.z == 0) ? C0  : (blockIdx.z == 1) ? C1  : C2;

#if HAS_TCGEN05
  uint32_t sb = smem_u32(smem);
  int wid = tid >> 5, lid = tid & 31;

  // TMEM allocation protocol: allocating warp allocates, then relinquishes the
  // permit so co-resident CTAs can allocate (CUTLASS protocol).
  if (wid == 0) { T5_ALLOC(sb, 128); T5_RELINQ(); }
  if (tid == 0) { MBAR_INIT(sb + 8, 1); }
  __syncthreads();
  uint32_t tmem;
  asm volatile("ld.shared.b32 %0, [%1];" : "=r"(tmem) : "r"(sb));

  for (int c = 0; c < GEMM_CHUNKS; c++){
    int k0 = c * 64;
    char* bp = smem + 1024;
    load_tile16(bp,          Ah, m0, k0, tid);   // A hi   (128 x 64 bf16)
    load_tile16(bp + 16384,  Al, m0, k0, tid);   // A lo
    load_tile16(bp + 32768,  Bh, n0, k0, tid);   // B hi   (rows = N dim, 128 x 64)
    load_tile16(bp + 49152,  Bl, n0, k0, tid);   // B lo
    FENCE_ASYNC();
    __syncthreads();

    if (wid == 0 && elect1()){
      uint64_t dah  = sdesc(sb + 1024);
      uint64_t dal  = sdesc(sb + 1024 + 16384);
      uint64_t dbh0 = sdesc(sb + 1024 + 32768);          // B rows 0..63
      uint64_t dbh1 = sdesc(sb + 1024 + 32768 + 8192);   // B rows 64..127
      uint64_t dbl0 = sdesc(sb + 1024 + 49152);
      uint64_t dbl1 = sdesc(sb + 1024 + 49152 + 8192);
      #pragma unroll
      for (int ks = 0; ks < 4; ks++){
        uint64_t off = 2*ks;
        uint32_t en0 = (c | ks) ? 1u : 0u;
        // D cols [0,64): A x B[0:64]
        mma_ss_f16(tmem,      dah + off, dbh0 + off, IDESC_128x64, en0);
        mma_ss_f16(tmem,      dal + off, dbh0 + off, IDESC_128x64, 1u);
        mma_ss_f16(tmem,      dah + off, dbl0 + off, IDESC_128x64, 1u);
        // D cols [64,128): A x B[64:128]
        mma_ss_f16(tmem + 64, dah + off, dbh1 + off, IDESC_128x64, en0);
        mma_ss_f16(tmem + 64, dal + off, dbh1 + off, IDESC_128x64, 1u);
        mma_ss_f16(tmem + 64, dah + off, dbl1 + off, IDESC_128x64, 1u);
      }
      T5_COMMIT(sb + 8);
    }
    MBAR_WAIT(sb + 8, c & 1);   // all threads: MMAs of chunk c done -> smem reusable
    __syncthreads();
  }

  T5_FENCE_AFTER();

  // epilogue: warp w owns D rows 32w..32w+31 (its TMEM subpartition)
  #pragma unroll
  for (int nb = 0; nb < 4; nb++){
    uint32_t r[32];
    LDTM_X32(r, tmem + nb*32);
    T5_WAIT_LD();
    float4* cp = (float4*)(C + (size_t)(m0 + wid*32 + lid) * 2048 + n0 + nb*32);
    #pragma unroll
    for (int q = 0; q < 8; q++)
      cp[q] = make_float4(__uint_as_float(r[4*q]),   __uint_as_float(r[4*q+1]),
                          __uint_as_float(r[4*q+2]), __uint_as_float(r[4*q+3]));
  }
  __syncthreads();
  if (tid == 0) { MBAR_INVAL(sb + 8); }
  __syncthreads();
  if (wid == 0) { T5_DEALLOC(tmem, 128); }

#else
  // ---- SIMT fallback (generic compile target; runs only if the sm_103a image
  //      is absent). Reconstructs A = Ah+Al, B = Bh+Bl in fp32. ----
  float* As = (float*)smem;            // [16][128] K-major (As[k][m])
  float* Bs = As + 16*128;             // [16][128] (Bs[k][n])
  int tx = tid & 7;                    // 8 col groups x 16 cols
  int ty = tid >> 3;                   // 16 row groups x 8 rows
  unsigned long long acc[8][8];
  #pragma unroll
  for (int j=0;j<8;j++)
    #pragma unroll
    for (int q=0;q<8;q++) acc[j][q] = 0ull;

  for (int k0 = 0; k0 < 2048; k0 += 16){
    #pragma unroll
    for (int i = 0; i < 16; i++){
      int e = tid + i*128;
      int row = e >> 4, col = e & 15;
      size_t gi = (size_t)(m0+row)*2048 + k0 + col;
      As[col*128 + row] = __bfloat162float(Ah[gi]) + __bfloat162float(Al[gi]);
    }
    #pragma unroll
    for (int i = 0; i < 16; i++){
      int e = tid + i*128;
      int kk = e >> 7, n = e & 127;
      size_t gi = (size_t)(n0+n)*2048 + k0 + kk;
      Bs[kk*128 + n] = __bfloat162float(Bh[gi]) + __bfloat162float(Bl[gi]);
    }
    __syncthreads();
    #pragma unroll
    for (int kk = 0; kk < 16; kk++){
      const unsigned long long* bp = (const unsigned long long*)(Bs + kk*128) + tx*8;
      float a[8];
      #pragma unroll
      for (int j=0;j<8;j++) a[j] = As[kk*128 + ty*8 + j];
      #pragma unroll
      for (int j=0;j<8;j++){
        unsigned long long ap = f2pack(a[j], a[j]);
        #pragma unroll
        for (int q=0;q<8;q++) acc[j][q] = fma2(ap, bp[q], acc[j][q]);
      }
    }
    __syncthreads();
  }
  #pragma unroll
  for (int j=0;j<8;j++){
    float* cp = C + (size_t)(m0 + ty*8 + j)*2048 + n0 + tx*16;
    #pragma unroll
    for (int q=0;q<8;q++){
      float2 v2 = f2unpack(acc[j][q]);
      cp[2*q] = v2.x; cp[2*q+1] = v2.y;
    }
  }
#endif
}

// ---------------- conversion kernels ----------------
__global__ void splitf(const float* __restrict__ s, __nv_bfloat16* __restrict__ hi,
                       __nv_bfloat16* __restrict__ lo, int n)
{
  int i = blockIdx.x*256 + threadIdx.x;
  if (i < n){
    float f = s[i];
    __nv_bfloat16 h = __float2bfloat16(f);
    hi[i] = h;
    lo[i] = __float2bfloat16(f - __bfloat162float(h));
  }
}

// transpose + split 4 weight matrices: Th[n][k]=bf16(W[k][n]), Tl = residual
__global__ void tsplit(const float* __restrict__ Wr, const float* __restrict__ Wk,
                       const float* __restrict__ Wv, const float* __restrict__ Wo,
                       __nv_bfloat16* __restrict__ out)
{
  const float* W = (blockIdx.z == 0) ? Wr : (blockIdx.z == 1) ? Wk : (blockIdx.z == 2) ? Wv : Wo;
  __nv_bfloat16* Th = out + (size_t)blockIdx.z * 2 * WSZ;
  __nv_bfloat16* Tl = Th + WSZ;
  __shared__ float s[32][33];
  int nb = blockIdx.x*32, kb = blockIdx.y*32;
  for (int r = threadIdx.y; r < 32; r += 8)
    s[r][threadIdx.x] = W[(size_t)(kb + r)*2048 + nb + threadIdx.x];
  __syncthreads();
  for (int r = threadIdx.y; r < 32; r += 8){
    float f = s[threadIdx.x][r];           // W[kb+tx][nb+r]
    __nv_bfloat16 h = __float2bfloat16(f);
    size_t oi = (size_t)(nb + r)*2048 + kb + threadIdx.x;
    Th[oi] = h;
    Tl[oi] = __float2bfloat16(f - __bfloat162float(h));
  }
}

// ---------------- SIMT GEMM (thin/mid projections) ----------------
__device__ __forceinline__ void gemm_core(
    const float* __restrict__ A, int lda,
    const float* __restrict__ B, float* __restrict__ C, int N,
    int kbegin, int kend, int m0, int n0,
    float (*As)[128], float (*Bs)[128])
{
  int tid = threadIdx.x;
  int tm = (tid >> 4) << 3;
  int tn = (tid & 15) << 3;
  unsigned long long acc[8][4];
  #pragma unroll
  for (int i=0;i<8;i++)
    #pragma unroll
    for (int q=0;q<4;q++) acc[i][q] = 0ull;

  for (int k0 = kbegin; k0 < kend; k0 += 16) {
    #pragma unroll
    for (int i=0;i<8;i++){
      int e = tid + i*256;
      int row = e >> 4, col = e & 15;
      As[col][row] = A[(size_t)(m0+row)*lda + k0 + col];
    }
    #pragma unroll
    for (int i=0;i<8;i++){
      int e = tid + i*256;
      int row = e >> 7, col = e & 127;
      int n = n0 + col;
      Bs[row][col] = (n < N) ? B[(size_t)(k0+row)*N + n] : 0.f;
    }
    __syncthreads();
    #pragma unroll
    for (int kk=0;kk<16;kk++){
      float4 a0 = *(const float4*)&As[kk][tm];
      float4 a1 = *(const float4*)&As[kk][tm+4];
      ulonglong2 b0 = *(const ulonglong2*)&Bs[kk][tn];
      ulonglong2 b1 = *(const ulonglong2*)&Bs[kk][tn+4];
      unsigned long long bp0 = b0.x, bp1 = b0.y, bp2 = b1.x, bp3 = b1.y;
      float av[8] = {a0.x,a0.y,a0.z,a0.w,a1.x,a1.y,a1.z,a1.w};
      #pragma unroll
      for (int i=0;i<8;i++){
        unsigned long long ap = f2pack(av[i], av[i]);
        acc[i][0] = fma2(ap, bp0, acc[i][0]);
        acc[i][1] = fma2(ap, bp1, acc[i][1]);
        acc[i][2] = fma2(ap, bp2, acc[i][2]);
        acc[i][3] = fma2(ap, bp3, acc[i][3]);
      }
    }
    __syncthreads();
  }
  #pragma unroll
  for (int i=0;i<8;i++){
    int m = m0 + tm + i;
    #pragma unroll
    for (int q=0;q<4;q++){
      float2 v2 = f2unpack(acc[i][q]);
      int n = n0 + tn + 2*q;
      if (n   < N) C[(size_t)m*N + n    ] = v2.x;
      if (n+1 < N) C[(size_t)m*N + n + 1] = v2.y;
    }
  }
}

__global__ void __launch_bounds__(256) sgemm3(
    const float* __restrict__ A, int lda,
    const float* B0, const float* B1, const float* B2,
    float* C0, float* C1, float* C2,
    int M, int N, int K)
{
  __shared__ float As[16][128];
  __shared__ float Bs[16][128];
  const float* B = (blockIdx.z == 0) ? B0 : (blockIdx.z == 1) ? B1 : B2;
  float*       C = (blockIdx.z == 0) ? C0 : (blockIdx.z == 1) ? C1 : C2;
  gemm_core(A, lda, B, C, N, 0, K, blockIdx.y*128, blockIdx.x*128, As, Bs);
}

__global__ void __launch_bounds__(256) sgemm_splitk(
    const float* __restrict__ A, int lda,
    const float* __restrict__ B, float* __restrict__ Cpart,
    int M, int N, int Kslice)
{
  __shared__ float As[16][128];
  __shared__ float Bs[16][128];
  int kb = blockIdx.z * Kslice;
  gemm_core(A, lda, B, Cpart + (size_t)blockIdx.z*M*N, N,
            kb, kb + Kslice, blockIdx.y*128, blockIdx.x*128, As, Bs);
}

// ---------------- small kernels ----------------
__global__ void build_bcat(const float* __restrict__ w1, const float* __restrict__ a1,
                           const float* __restrict__ v1, float* __restrict__ bcat)
{
  int i = blockIdx.x*256 + threadIdx.x;
  if (i >= 2048*256) return;
  int row = i >> 8, col = i & 255;
  float val;
  if      (col <  96) val = w1[row*96 + col];
  else if (col < 192) val = a1[row*96 + col - 96];
  else                val = v1[row*64 + col - 192];
  bcat[i] = val;
}

__global__ void reduce_hcat(const float* __restrict__ part, float* __restrict__ hcat)
{
  int i = blockIdx.x*256 + threadIdx.x;
  if (i >= 1024*256) return;
  float s = 0.f;
  #pragma unroll
  for (int z = 0; z < 8; z++) s += part[(size_t)z*1024*256 + i];
  int col = i & 255;
  if (col < 96) s = tanhf(s);
  hcat[i] = s;
}

__device__ __forceinline__ float sigmoidf_(float x){ return 1.f/(1.f + expf(-x)); }

__global__ void __launch_bounds__(64) prep_kernel(
    float* __restrict__ k, float* __restrict__ v,
    const float* __restrict__ gw, const float* __restrict__ ga, const float* __restrict__ gv,
    const float* __restrict__ v_first, const float* __restrict__ mask,
    const float* __restrict__ w0, const float* __restrict__ a0, const float* __restrict__ v0,
    const float* __restrict__ k_k, const float* __restrict__ k_a,
    float* __restrict__ dec, float* __restrict__ asc, float* __restrict__ bsc,
    float* __restrict__ ksc, float* __restrict__ vsc)
{
  int t = blockIdx.x >> 5;
  int h = blockIdx.x & 31;
  int tid = threadIdx.x;
  int c = (h << 6) | tid;
  int idx = t*Cc + c;

  float kr  = k[idx];
  float kkv = kr * k_k[c];

  __shared__ float red[64];
  red[tid] = kkv*kkv;
  __syncthreads();
  #pragma unroll
  for (int s = 32; s > 0; s >>= 1){
    if (tid < s) red[tid] += red[tid + s];
    __syncthreads();
  }
  float kkn = kkv / fmaxf(sqrtf(red[0]), 1e-12f);

  float av = sigmoidf_(a0[c] + ga[idx]);
  float m  = mask[t];

  float y  = w0[c] + gw[idx];
  float z  = -y;
  float sp = (z > 20.f) ? z : log1pf(expf(z));
  float w  = -sp - 0.6f;
  float d  = expf(-expf(w));
  d = d*m + (1.f - m);

  float vr = v[idx];
  float sv = sigmoidf_(v0[c] + gv[idx]);
  float vm = fmaf(v_first[idx] - vr, sv, vr);

  float ku = kr * fmaf(av - 1.f, k_a[c], 1.f);

  k[idx]   = ku;
  v[idx]   = vm;
  dec[idx] = d;
  ksc[idx] = ku * m;
  vsc[idx] = vm * m;
  asc[idx] = -kkn * m;
  bsc[idx] = kkn * av * m;
}

__global__ void __launch_bounds__(64) scan_kernel(
    const float* __restrict__ dec, const float* __restrict__ r,
    const float* __restrict__ kq, const float* __restrict__ vq,
    const float* __restrict__ aq, const float* __restrict__ bq,
    float* __restrict__ o)
{
  int h = blockIdx.x;
  int tid = threadIdx.x;
  __shared__ float sb[2][6][64];
  unsigned long long S[32];
  #pragma unroll
  for (int j=0;j<32;j++) S[j] = 0ull;

  int base = (h << 6) + tid;
  float pre[6];
  pre[0]=dec[base]; pre[1]=r[base]; pre[2]=kq[base];
  pre[3]=vq[base];  pre[4]=aq[base]; pre[5]=bq[base];

  for (int t = 0; t < Tt; t++){
    int p = t & 1;
    sb[p][0][tid]=pre[0]; sb[p][1][tid]=pre[1]; sb[p][2][tid]=pre[2];
    sb[p][3][tid]=pre[3]; sb[p][4][tid]=pre[4]; sb[p][5][tid]=pre[5];
    __syncthreads();
    if (t < Tt-1){
      int nb = (t+1)*Cc + base;
      pre[0]=dec[nb]; pre[1]=r[nb]; pre[2]=kq[nb];
      pre[3]=vq[nb];  pre[4]=aq[nb]; pre[5]=bq[nb];
    }
    const unsigned long long* dd = (const unsigned long long*)sb[p][0];
    const unsigned long long* rr = (const unsigned long long*)sb[p][1];
    const unsigned long long* kk = (const unsigned long long*)sb[p][2];
    const unsigned long long* aa = (const unsigned long long*)sb[p][4];
    const unsigned long long* bb = (const unsigned long long*)sb[p][5];

    unsigned long long acc0 = 0ull, acc1 = 0ull;
    #pragma unroll
    for (int j=0;j<32;j+=2){
      acc0 = fma2(S[j],   aa[j],   acc0);
      acc1 = fma2(S[j+1], aa[j+1], acc1);
    }
    float2 u0 = f2unpack(acc0), u1 = f2unpack(acc1);
    float sa = (u0.x + u0.y) + (u1.x + u1.y);

    float vi = sb[p][3][tid];
    unsigned long long sa2 = f2pack(sa, sa);
    unsigned long long vi2 = f2pack(vi, vi);

    unsigned long long oa0 = 0ull, oa1 = 0ull;
    #pragma unroll
    for (int j=0;j<32;j+=2){
      S[j]   = fma2(S[j],   dd[j],   fma2(sa2, bb[j],   mul2(vi2, kk[j])));
      oa0    = fma2(S[j],   rr[j],   oa0);
      S[j+1] = fma2(S[j+1], dd[j+1], fma2(sa2, bb[j+1], mul2(vi2, kk[j+1])));
      oa1    = fma2(S[j+1], rr[j+1], oa1);
    }
    float2 w0_ = f2unpack(oa0), w1_ = f2unpack(oa1);
    o[t*Cc + base] = (w0_.x + w0_.y) + (w1_.x + w1_.y);
  }
}

__global__ void __launch_bounds__(64) post_kernel(
    const float* __restrict__ r, const float* __restrict__ k,
    const float* __restrict__ v, const float* __restrict__ r_k,
    float* __restrict__ o)
{
  int t = blockIdx.x >> 5;
  int h = blockIdx.x & 31;
  int tid = threadIdx.x;
  int c = (h << 6) | tid;
  int idx = t*Cc + c;
  __shared__ float red[64];
  red[tid] = r[idx]*k[idx]*r_k[c];
  __syncthreads();
  #pragma unroll
  for (int s = 32; s > 0; s >>= 1){
    if (tid < s) red[tid] += red[tid + s];
    __syncthreads();
  }
  o[idx] += red[0]*v[idx];
}

__global__ void copy_vfirst(const float* __restrict__ vf, float* __restrict__ out)
{
  int i = blockIdx.x*256 + threadIdx.x;
  if (i < TC) out[i] = vf[i];
}

// ---------------- host launcher ----------------
extern "C" void kernel_launch(void* const* d_in, const int* in_sizes, int n_in,
                              void* d_out, int out_size)
{
  const float* x        = (const float*)d_in[0];
  const float* v_first  = (const float*)d_in[1];
  const float* mask     = (const float*)d_in[2];
  const float* w0       = (const float*)d_in[3];
  const float* w1       = (const float*)d_in[4];
  const float* w2       = (const float*)d_in[5];
  const float* a0       = (const float*)d_in[6];
  const float* a1       = (const float*)d_in[7];
  const float* a2       = (const float*)d_in[8];
  const float* v0       = (const float*)d_in[9];
  const float* v1       = (const float*)d_in[10];
  const float* v2       = (const float*)d_in[11];
  const float* k_k      = (const float*)d_in[12];
  const float* k_a      = (const float*)d_in[13];
  const float* r_k      = (const float*)d_in[14];
  const float* Wr       = (const float*)d_in[15];
  const float* Wk       = (const float*)d_in[16];
  const float* Wv       = (const float*)d_in[17];
  const float* Wo       = (const float*)d_in[18];
  float* outf = (float*)d_out;

  float* S = nullptr;
  cudaGetSymbolAddress((void**)&S, g_scratch);
  __nv_bfloat16* BF = nullptr;
  cudaGetSymbolAddress((void**)&BF, g_bf16);

  float* bcat = S;
  float* part = bcat + 524288;
  float* hcat = part + 2097152;
  float* gw   = hcat + 262144;
  float* ga   = gw  + TC;
  float* gv   = ga  + TC;
  float* r    = gv  + TC;
  float* k    = r   + TC;
  float* v    = k   + TC;
  float* dec  = v   + TC;
  float* asc  = dec + TC;
  float* bsc  = asc + TC;
  float* ksc  = bsc + TC;
  float* vsc  = ksc + TC;
  float* o    = vsc + TC;

  __nv_bfloat16* xh = BF;
  __nv_bfloat16* xl = xh + TC;
  __nv_bfloat16* oh = xl + TC;
  __nv_bfloat16* ol = oh + TC;
  __nv_bfloat16* Wt = ol + TC;           // [Wr_h, Wr_l, Wk_h, Wk_l, Wv_h, Wv_l, Wo_h, Wo_l]
  __nv_bfloat16* Wrh = Wt + 0*WSZ, *Wrl = Wt + 1*WSZ;
  __nv_bfloat16* Wkh = Wt + 2*WSZ, *Wkl = Wt + 3*WSZ;
  __nv_bfloat16* Wvh = Wt + 4*WSZ, *Wvl = Wt + 5*WSZ;
  __nv_bfloat16* Woh = Wt + 6*WSZ, *Wol = Wt + 7*WSZ;

  cudaFuncSetAttribute(gemm_tc, cudaFuncAttributeMaxDynamicSharedMemorySize, GEMM_SMEM_ALLOC);

  // 0) weight transpose+split and x split (tensor-core operand prep)
  tsplit<<<dim3(64,64,4), dim3(32,8)>>>(Wr, Wk, Wv, Wo, Wt);
  splitf<<<TC/256, 256>>>(x, xh, xl, TC);

  // 1) concat thin weights: bcat = [w1 | a1 | v1]
  build_bcat<<<2048, 256>>>(w1, a1, v1, bcat);

  // 2) hcat_pre = x @ bcat via split-K(8)
  {
    dim3 grid(2, 8, 8);
    sgemm_splitk<<<grid, 256>>>(x, Cc, bcat, part, 1024, 256, 256);
  }
  // 3) reduce partials (+ tanh on w-path)
  reduce_hcat<<<1024, 256>>>(part, hcat);

  // 4) mid GEMMs
  {
    dim3 grid(16, 8, 1);
    sgemm3<<<grid, 256>>>(hcat,       256, w2, w2, w2, gw, gw, gw, 1024, Cc, 96);
    sgemm3<<<grid, 256>>>(hcat + 96,  256, a2, a2, a2, ga, ga, ga, 1024, Cc, 96);
    sgemm3<<<grid, 256>>>(hcat + 192, 256, v2, v2, v2, gv, gv, gv, 1024, Cc, 64);
  }

  // 5) big GEMMs on tcgen05: r,k,v = x @ {Wr,Wk,Wv} (split-bf16)
  {
    dim3 grid(16, 8, 3);
    gemm_tc<<<grid, 128, GEMM_SMEM_ALLOC>>>(xh, xl, Wrh, Wrl, Wkh, Wkl, Wvh, Wvl, r, k, v);
  }

  // 6) elementwise prep
  prep_kernel<<<Tt*Hh, 64>>>(k, v, gw, ga, gv, v_first, mask,
                             w0, a0, v0, k_k, k_a,
                             dec, asc, bsc, ksc, vsc);

  // 7) sequential scan
  scan_kernel<<<Hh, 64>>>(dec, r, ksc, vsc, asc, bsc, o);

  // 8) residual
  post_kernel<<<Tt*Hh, 64>>>(r, k, v, r_k, o);

  // 9) final GEMM on tcgen05: out = o @ Wo
  splitf<<<TC/256, 256>>>(o, oh, ol, TC);
  {
    dim3 grid(16, 8, 1);
    gemm_tc<<<grid, 128, GEMM_SMEM_ALLOC>>>(oh, ol, Woh, Wol, Woh, Wol, Woh, Wol, outf, outf, outf);
  }

  // 10) v_first pass-through
  if (out_size >= 2*TC) {
    copy_vfirst<<<(TC + 255)/256, 256>>>(v_first, outf + TC);
  }
}

// round 6
// speedup vs baseline: 1.7249x; 1.1149x over previous
#include <cuda_runtime.h>
#include <cuda_bf16.h>
#include <math.h>
#include <stdint.h>

// Problem constants
#define Tt 1024
#define Cc 2048
#define Hh 32
#define Nn 64
#define TC (Tt*Cc)          // 2097152

// tcgen05 available only in architecture-specific compilation passes
#if defined(__CUDA_ARCH_FEAT_SM103_ALL) || defined(__CUDA_ARCH_FEAT_SM100_ALL) || defined(__CUDA_ARCH_SPECIFIC__)
#define HAS_TCGEN05 1
#else
#define HAS_TCGEN05 0
#endif

// ---------------- packed f32x2 helpers ----------------
__device__ __forceinline__ unsigned long long f2pack(float x, float y){
  unsigned long long r;
  asm("mov.b64 %0, {%1, %2};" : "=l"(r) : "r"(__float_as_uint(x)), "r"(__float_as_uint(y)));
  return r;
}
__device__ __forceinline__ float2 f2unpack(unsigned long long p){
  unsigned int lo, hi;
  asm("mov.b64 {%0, %1}, %2;" : "=r"(lo), "=r"(hi) : "l"(p));
  return make_float2(__uint_as_float(lo), __uint_as_float(hi));
}
__device__ __forceinline__ unsigned long long fma2(unsigned long long a, unsigned long long b, unsigned long long c){
  unsigned long long d;
  asm("fma.rn.f32x2 %0, %1, %2, %3;" : "=l"(d) : "l"(a), "l"(b), "l"(c));
  return d;
}
__device__ __forceinline__ unsigned long long mul2(unsigned long long a, unsigned long long b){
  unsigned long long d;
  asm("mul.rn.f32x2 %0, %1, %2;" : "=l"(d) : "l"(a), "l"(b));
  return d;
}

// ---------------- tcgen05 / mbarrier helpers (sm_103a) ----------------
__device__ __forceinline__ uint32_t smem_u32(const void* p){
  uint32_t a;
  asm("{ .reg .u64 t; cvta.to.shared.u64 t, %1; cvt.u32.u64 %0, t; }" : "=r"(a) : "l"(p));
  return a;
}

#define SW128(x) ((x) ^ (((x) >> 3) & 0x70))

#if HAS_TCGEN05
__device__ __forceinline__ uint32_t elect1(){
  uint32_t r;
  asm volatile("{\n\t.reg .pred p;\n\telect.sync _|p, 0xFFFFFFFF;\n\tselp.b32 %0, 1, 0, p;\n\t}" : "=r"(r));
  return r;
}

#define T5_ALLOC(sa, n)   asm volatile("tcgen05.alloc.cta_group::1.sync.aligned.shared::cta.b32 [%0], %1;" :: "r"(sa), "r"(n) : "memory")
#define T5_DEALLOC(t, n)  asm volatile("tcgen05.dealloc.cta_group::1.sync.aligned.b32 %0, %1;" :: "r"(t), "r"(n))
#define T5_RELINQ()       asm volatile("tcgen05.relinquish_alloc_permit.cta_group::1.sync.aligned;")
#define T5_COMMIT(mb)     asm volatile("tcgen05.commit.cta_group::1.mbarrier::arrive::one.shared::cluster.b64 [%0];" :: "r"(mb) : "memory")
#define T5_FENCE_AFTER()  asm volatile("tcgen05.fence::after_thread_sync;" ::: "memory")
#define T5_WAIT_LD()      asm volatile("tcgen05.wait::ld.sync.aligned;" ::: "memory")
#define FENCE_ASYNC()     asm volatile("fence.proxy.async.shared::cta;" ::: "memory")

#define MBAR_INIT(mb, cnt) asm volatile("mbarrier.init.shared.b64 [%0], %1;" :: "r"(mb), "r"(cnt) : "memory")
#define MBAR_INVAL(mb)     asm volatile("mbarrier.inval.shared.b64 [%0];" :: "r"(mb) : "memory")

#define MBAR_WAIT(mb, ph) do { \
  uint32_t _m = (mb), _p = (ph), _d; \
  asm volatile("{\n\t.reg .pred p;\n\tmbarrier.try_wait.parity.acquire.cta.shared::cta.b64 p, [%1], %2;\n\tselp.b32 %0, 1, 0, p;\n\t}" \
               : "=r"(_d) : "r"(_m), "r"(_p) : "memory"); \
  while (!_d) { \
    asm volatile("{\n\t.reg .pred p;\n\tmbarrier.try_wait.parity.acquire.cta.shared::cta.b64 p, [%1], %2, 0x989680;\n\tselp.b32 %0, 1, 0, p;\n\t}" \
                 : "=r"(_d) : "r"(_m), "r"(_p) : "memory"); \
  } } while(0)

#define LDTM_X32(r, ta) \
    asm volatile( \
        "tcgen05.ld.sync.aligned.32x32b.x32.b32 " \
        "{%0, %1, %2, %3, %4, %5, %6, %7, " \
        " %8, %9, %10, %11, %12, %13, %14, %15, " \
        " %16, %17, %18, %19, %20, %21, %22, %23, " \
        " %24, %25, %26, %27, %28, %29, %30, %31}, [%32];" \
        : "=r"((r)[0]),  "=r"((r)[1]),  "=r"((r)[2]),  "=r"((r)[3]), \
          "=r"((r)[4]),  "=r"((r)[5]),  "=r"((r)[6]),  "=r"((r)[7]), \
          "=r"((r)[8]),  "=r"((r)[9]),  "=r"((r)[10]), "=r"((r)[11]), \
          "=r"((r)[12]), "=r"((r)[13]), "=r"((r)[14]), "=r"((r)[15]), \
          "=r"((r)[16]), "=r"((r)[17]), "=r"((r)[18]), "=r"((r)[19]), \
          "=r"((r)[20]), "=r"((r)[21]), "=r"((r)[22]), "=r"((r)[23]), \
          "=r"((r)[24]), "=r"((r)[25]), "=r"((r)[26]), "=r"((r)[27]), \
          "=r"((r)[28]), "=r"((r)[29]), "=r"((r)[30]), "=r"((r)[31]) \
        : "r"(ta))

__device__ __forceinline__ uint64_t sdesc(uint32_t addr){
  const uint64_t base = (2ull << 61) | (1ull << 46) | (64ull << 32) | (1ull << 16);
  return base | ((uint64_t)(addr >> 4) & 0x3FFF);
}

__device__ __forceinline__ void mma_ss_f16(uint32_t d, uint64_t ad, uint64_t bd, uint32_t idesc, uint32_t en){
  asm volatile(
    "{\n\t.reg .pred p;\n\tsetp.ne.u32 p, %5, 0;\n\t"
    "tcgen05.mma.cta_group::1.kind::f16 [%0], %1, %2, %3, {%4, %4, %4, %4}, p;\n\t}"
    :: "r"(d), "l"(ad), "l"(bd), "r"(idesc), "r"(0u), "r"(en) : "memory");
}

// idesc: dtype F32, atype/btype BF16, N=64, M=128 (proven atom geometry)
#define IDESC_128x64 ((1u<<4) | (1u<<7) | (1u<<10) | ((64u/8u)<<17) | ((128u/16u)<<24))
#endif // HAS_TCGEN05

// ---------------- scratch (device globals; no allocations allowed) ----------------
#define SCRATCH_FLOATS (524288 + 2097152 + 262144 + 12*TC)
__device__ float g_scratch[SCRATCH_FLOATS];

// bf16 pool: xh,xl,oh,ol (4*TC) + 8 weight splits (8*WSZ) + operand extras
#define WSZ (2048*2048)
#define BF_EXTRA (2*524288 /*bcT*/ + 4*262144 /*w2T,a2T*/ + 2*131072 /*v2T*/ + 2*262144 /*hc*/)
__device__ __align__(16) __nv_bfloat16 g_bf16[4*TC + 8*WSZ + BF_EXTRA];

// ---------------- generalized tcgen05 split-bf16 GEMM ----------------
// C[m][n] = sum_k (Ah+Al)[m][akoff+k] * (Bh+Bl)[n][bkoff+k], 128x128 tile per CTA,
// K chunks of 64 bf16 (SW128 K-major smem tiles). Serialized chunk loop, 1 CTA/SM.
// z-dim: if kslice>0 -> split-K (B/C from slot 0, koff=z*kslice, C+=z*cslice);
// else z selects (B,C) triple and A column offset acol0 + z*acolz.
#define GEMM_SMEM_ALLOC 163840

__device__ __forceinline__ void load_tile16g(char* dst, const __nv_bfloat16* __restrict__ g,
                                             int row0, int col0, int ld, int tid){
  #pragma unroll
  for (int i = 0; i < 8; i++){
    int e = tid + (i << 7);
    int row = e >> 3, seg = e & 7;
    uint4 v = *(const uint4*)(g + (size_t)(row0 + row)*ld + col0 + (seg << 3));
    *(uint4*)(dst + SW128(row*128 + seg*16)) = v;
  }
}

__global__ void __launch_bounds__(128)
#if HAS_TCGEN05
__cluster_dims__(1, 1, 1)
#endif
gemm_tcg(
    const __nv_bfloat16* __restrict__ Ah, const __nv_bfloat16* __restrict__ Al, int lda,
    const __nv_bfloat16* __restrict__ Bh0, const __nv_bfloat16* __restrict__ Bl0,
    const __nv_bfloat16* __restrict__ Bh1, const __nv_bfloat16* __restrict__ Bl1,
    const __nv_bfloat16* __restrict__ Bh2, const __nv_bfloat16* __restrict__ Bl2, int ldb,
    float* C0, float* C1, float* C2, int ldc,
    int kchunks, int kslice, long long cslice, int acol0, int acolz)
{
  extern __shared__ __align__(1024) char smem[];
  int tid = threadIdx.x;
  int z = blockIdx.z;
  int m0 = blockIdx.y * 128, n0 = blockIdx.x * 128;

  const __nv_bfloat16 *Bh, *Bl;
  float* C;
  int akoff, bkoff;
  if (kslice > 0){
    Bh = Bh0; Bl = Bl0;
    C = C0 + (long long)z * cslice;
    akoff = acol0 + z * kslice;
    bkoff = z * kslice;
  } else {
    Bh = (z == 0) ? Bh0 : (z == 1) ? Bh1 : Bh2;
    Bl = (z == 0) ? Bl0 : (z == 1) ? Bl1 : Bl2;
    C  = (z == 0) ? C0  : (z == 1) ? C1  : C2;
    akoff = acol0 + z * acolz;
    bkoff = 0;
  }

#if HAS_TCGEN05
  uint32_t sb = smem_u32(smem);
  int wid = tid >> 5, lid = tid & 31;

  if (wid == 0) { T5_ALLOC(sb, 128); T5_RELINQ(); }
  if (tid == 0) { MBAR_INIT(sb + 8, 1); }
  __syncthreads();
  uint32_t tmem;
  asm volatile("ld.shared.b32 %0, [%1];" : "=r"(tmem) : "r"(sb));

  for (int c = 0; c < kchunks; c++){
    int k0 = c * 64;
    char* bp = smem + 1024;
    load_tile16g(bp,          Ah, m0, akoff + k0, lda, tid);   // A hi
    load_tile16g(bp + 16384,  Al, m0, akoff + k0, lda, tid);   // A lo
    load_tile16g(bp + 32768,  Bh, n0, bkoff + k0, ldb, tid);   // B hi
    load_tile16g(bp + 49152,  Bl, n0, bkoff + k0, ldb, tid);   // B lo
    FENCE_ASYNC();
    __syncthreads();

    if (wid == 0 && elect1()){
      uint64_t dah  = sdesc(sb + 1024);
      uint64_t dal  = sdesc(sb + 1024 + 16384);
      uint64_t dbh0 = sdesc(sb + 1024 + 32768);
      uint64_t dbh1 = sdesc(sb + 1024 + 32768 + 8192);
      uint64_t dbl0 = sdesc(sb + 1024 + 49152);
      uint64_t dbl1 = sdesc(sb + 1024 + 49152 + 8192);
      #pragma unroll
      for (int ks = 0; ks < 4; ks++){
        uint64_t off = 2*ks;
        uint32_t en0 = (c | ks) ? 1u : 0u;
        mma_ss_f16(tmem,      dah + off, dbh0 + off, IDESC_128x64, en0);
        mma_ss_f16(tmem,      dal + off, dbh0 + off, IDESC_128x64, 1u);
        mma_ss_f16(tmem,      dah + off, dbl0 + off, IDESC_128x64, 1u);
        mma_ss_f16(tmem + 64, dah + off, dbh1 + off, IDESC_128x64, en0);
        mma_ss_f16(tmem + 64, dal + off, dbh1 + off, IDESC_128x64, 1u);
        mma_ss_f16(tmem + 64, dah + off, dbl1 + off, IDESC_128x64, 1u);
      }
      T5_COMMIT(sb + 8);
    }
    MBAR_WAIT(sb + 8, c & 1);
    __syncthreads();
  }

  T5_FENCE_AFTER();

  #pragma unroll
  for (int nb = 0; nb < 4; nb++){
    uint32_t r[32];
    LDTM_X32(r, tmem + nb*32);
    T5_WAIT_LD();
    float4* cp = (float4*)(C + (size_t)(m0 + wid*32 + lid) * ldc + n0 + nb*32);
    #pragma unroll
    for (int q = 0; q < 8; q++)
      cp[q] = make_float4(__uint_as_float(r[4*q]),   __uint_as_float(r[4*q+1]),
                          __uint_as_float(r[4*q+2]), __uint_as_float(r[4*q+3]));
  }
  __syncthreads();
  if (tid == 0) { MBAR_INVAL(sb + 8); }
  __syncthreads();
  if (wid == 0) { T5_DEALLOC(tmem, 128); }

#else
  // Generic-pass fallback (never selected at runtime on sm_103a; correctness-only).
  int K = kchunks * 64;
  for (int idx = tid; idx < 128*128; idx += 128){
    int mi = idx >> 7, ni = idx & 127;
    float s = 0.f;
    for (int k = 0; k < K; k++){
      float av = __bfloat162float(Ah[(size_t)(m0+mi)*lda + akoff + k]) +
                 __bfloat162float(Al[(size_t)(m0+mi)*lda + akoff + k]);
      float bv = __bfloat162float(Bh[(size_t)(n0+ni)*ldb + bkoff + k]) +
                 __bfloat162float(Bl[(size_t)(n0+ni)*ldb + bkoff + k]);
      s += av * bv;
    }
    C[(size_t)(m0+mi)*ldc + n0 + ni] = s;
  }
#endif
}

// ---------------- operand-prep kernels ----------------
__global__ void splitf(const float* __restrict__ s, __nv_bfloat16* __restrict__ hi,
                       __nv_bfloat16* __restrict__ lo, int n)
{
  int i = blockIdx.x*256 + threadIdx.x;
  if (i < n){
    float f = s[i];
    __nv_bfloat16 h = __float2bfloat16(f);
    hi[i] = h;
    lo[i] = __float2bfloat16(f - __bfloat162float(h));
  }
}

// transpose + split 4 big weight matrices: Th[n][k]=bf16(W[k][n]), Tl = residual
__global__ void tsplit(const float* __restrict__ Wr, const float* __restrict__ Wk,
                       const float* __restrict__ Wv, const float* __restrict__ Wo,
                       __nv_bfloat16* __restrict__ out)
{
  const float* W = (blockIdx.z == 0) ? Wr : (blockIdx.z == 1) ? Wk : (blockIdx.z == 2) ? Wv : Wo;
  __nv_bfloat16* Th = out + (size_t)blockIdx.z * 2 * WSZ;
  __nv_bfloat16* Tl = Th + WSZ;
  __shared__ float s[32][33];
  int nb = blockIdx.x*32, kb = blockIdx.y*32;
  for (int r = threadIdx.y; r < 32; r += 8)
    s[r][threadIdx.x] = W[(size_t)(kb + r)*2048 + nb + threadIdx.x];
  __syncthreads();
  for (int r = threadIdx.y; r < 32; r += 8){
    float f = s[threadIdx.x][r];
    __nv_bfloat16 h = __float2bfloat16(f);
    size_t oi = (size_t)(nb + r)*2048 + kb + threadIdx.x;
    Th[oi] = h;
    Tl[oi] = __float2bfloat16(f - __bfloat162float(h));
  }
}

// bcT[n][k] = [w1|a1|v1]^T split to bf16 hi/lo ; n<256, k<2048
__global__ void build_bcatT(const float* __restrict__ w1, const float* __restrict__ a1,
                            const float* __restrict__ v1,
                            __nv_bfloat16* __restrict__ Th, __nv_bfloat16* __restrict__ Tl)
{
  int i = blockIdx.x*256 + threadIdx.x;
  if (i >= 256*2048) return;
  int n = i >> 11, k = i & 2047;
  float f;
  if      (n <  96) f = w1[k*96 + n];
  else if (n < 192) f = a1[k*96 + n - 96];
  else              f = v1[k*64 + n - 192];
  __nv_bfloat16 h = __float2bfloat16(f);
  Th[i] = h;
  Tl[i] = __float2bfloat16(f - __bfloat162float(h));
}

// mid-weight transposes, zero-padded in k: w2T/a2T [2048,128] (K=96), v2T [2048,64] (K=64)
__global__ void build_m2T(const float* __restrict__ w2, const float* __restrict__ a2,
                          const float* __restrict__ v2,
                          __nv_bfloat16* __restrict__ w2Th, __nv_bfloat16* __restrict__ w2Tl,
                          __nv_bfloat16* __restrict__ a2Th, __nv_bfloat16* __restrict__ a2Tl,
                          __nv_bfloat16* __restrict__ v2Th, __nv_bfloat16* __restrict__ v2Tl)
{
  int z = blockIdx.z;
  int ldk = (z == 2) ? 64 : 128;
  int Kz  = (z == 2) ? 64 : 96;
  int nel = 2048 * ldk;
  int i = blockIdx.x*256 + threadIdx.x;
  if (i >= nel) return;
  int kp = i & (ldk - 1), n = i / ldk;
  const float* M = (z == 0) ? w2 : (z == 1) ? a2 : v2;
  float f = (kp < Kz) ? M[(size_t)kp*2048 + n] : 0.f;
  __nv_bfloat16 h = __float2bfloat16(f);
  __nv_bfloat16* Th = (z == 0) ? w2Th : (z == 1) ? a2Th : v2Th;
  __nv_bfloat16* Tl = (z == 0) ? w2Tl : (z == 1) ? a2Tl : v2Tl;
  Th[i] = h;
  Tl[i] = __float2bfloat16(f - __bfloat162float(h));
}

// reduce split-K partials (+ tanh on w-path) -> bf16 hi/lo hcat
__global__ void reduce_hcat(const float* __restrict__ part,
                            __nv_bfloat16* __restrict__ hch, __nv_bfloat16* __restrict__ hcl)
{
  int i = blockIdx.x*256 + threadIdx.x;
  if (i >= 1024*256) return;
  float s = 0.f;
  #pragma unroll
  for (int z = 0; z < 8; z++) s += part[(size_t)z*1024*256 + i];
  int col = i & 255;
  if (col < 96) s = tanhf(s);
  __nv_bfloat16 h = __float2bfloat16(s);
  hch[i] = h;
  hcl[i] = __float2bfloat16(s - __bfloat162float(h));
}

// ---------------- elementwise / scan kernels ----------------
__device__ __forceinline__ float sigmoidf_(float x){ return 1.f/(1.f + expf(-x)); }

__global__ void __launch_bounds__(64) prep_kernel(
    float* __restrict__ k, float* __restrict__ v,
    const float* __restrict__ gw, const float* __restrict__ ga, const float* __restrict__ gv,
    const float* __restrict__ v_first, const float* __restrict__ mask,
    const float* __restrict__ w0, const float* __restrict__ a0, const float* __restrict__ v0,
    const float* __restrict__ k_k, const float* __restrict__ k_a,
    float* __restrict__ dec, float* __restrict__ asc, float* __restrict__ bsc,
    float* __restrict__ ksc, float* __restrict__ vsc)
{
  int t = blockIdx.x >> 5;
  int h = blockIdx.x & 31;
  int tid = threadIdx.x;
  int c = (h << 6) | tid;
  int idx = t*Cc + c;

  float kr  = k[idx];
  float kkv = kr * k_k[c];

  __shared__ float red[64];
  red[tid] = kkv*kkv;
  __syncthreads();
  #pragma unroll
  for (int s = 32; s > 0; s >>= 1){
    if (tid < s) red[tid] += red[tid + s];
    __syncthreads();
  }
  float kkn = kkv / fmaxf(sqrtf(red[0]), 1e-12f);

  float av = sigmoidf_(a0[c] + ga[idx]);
  float m  = mask[t];

  float y  = w0[c] + gw[idx];
  float z  = -y;
  float sp = (z > 20.f) ? z : log1pf(expf(z));
  float w  = -sp - 0.6f;
  float d  = expf(-expf(w));
  d = d*m + (1.f - m);

  float vr = v[idx];
  float sv = sigmoidf_(v0[c] + gv[idx]);
  float vm = fmaf(v_first[idx] - vr, sv, vr);

  float ku = kr * fmaf(av - 1.f, k_a[c], 1.f);

  k[idx]   = ku;
  v[idx]   = vm;
  dec[idx] = d;
  ksc[idx] = ku * m;
  vsc[idx] = vm * m;
  asc[idx] = -kkn * m;
  bsc[idx] = kkn * av * m;
}

// RWKV-7 scan: one block per head, 128 threads (4 warps = 1/SMSP).
// Thread pair (2r, 2r+1) owns state row r, columns [0,32)/[32,64) as 16 packed f32x2.
// Cross-half reductions via shfl.bfly(1) (same warp).
__global__ void __launch_bounds__(128) scan_kernel(
    const float* __restrict__ dec, const float* __restrict__ r,
    const float* __restrict__ kq, const float* __restrict__ vq,
    const float* __restrict__ aq, const float* __restrict__ bq,
    float* __restrict__ o)
{
  int h = blockIdx.x;
  int tid = threadIdx.x;           // 0..127
  int row = tid >> 1, half = tid & 1;
  int hb = (h << 6);
  __shared__ float sb[2][6][64];

  unsigned long long S[16];
  #pragma unroll
  for (int j = 0; j < 16; j++) S[j] = 0ull;

  int c   = tid & 63;              // channel handled in load phase
  int grp = tid >> 6;              // 0 -> arrays {dec,r,kq}, 1 -> {vq,aq,bq}
  float pre0, pre1, pre2;
  {
    int nb = hb + c;
    if (grp == 0){ pre0 = dec[nb]; pre1 = r[nb];  pre2 = kq[nb]; }
    else         { pre0 = vq[nb];  pre1 = aq[nb]; pre2 = bq[nb]; }
  }

  for (int t = 0; t < Tt; t++){
    int p = t & 1;
    if (grp == 0){ sb[p][0][c] = pre0; sb[p][1][c] = pre1; sb[p][2][c] = pre2; }
    else         { sb[p][3][c] = pre0; sb[p][4][c] = pre1; sb[p][5][c] = pre2; }
    __syncthreads();
    if (t < Tt-1){
      int nb = (t+1)*Cc + hb + c;
      if (grp == 0){ pre0 = dec[nb]; pre1 = r[nb];  pre2 = kq[nb]; }
      else         { pre0 = vq[nb];  pre1 = aq[nb]; pre2 = bq[nb]; }
    }

    const unsigned long long* dd = (const unsigned long long*)(&sb[p][0][0]) + half*16;
    const unsigned long long* rr = (const unsigned long long*)(&sb[p][1][0]) + half*16;
    const unsigned long long* kk = (const unsigned long long*)(&sb[p][2][0]) + half*16;
    const unsigned long long* aa = (const unsigned long long*)(&sb[p][4][0]) + half*16;
    const unsigned long long* bb = (const unsigned long long*)(&sb[p][5][0]) + half*16;
    float vi = sb[p][3][row];
    unsigned long long vi2 = f2pack(vi, vi);

    // sa partials (4 acc trees) + vk = v*k ; then vk = S*d + vk (independent of sa)
    unsigned long long sA0=0ull, sA1=0ull, sA2=0ull, sA3=0ull;
    unsigned long long vk[16];
    #pragma unroll
    for (int j = 0; j < 16; j += 4){
      sA0 = fma2(S[j],   aa[j],   sA0);  vk[j]   = mul2(vi2, kk[j]);
      sA1 = fma2(S[j+1], aa[j+1], sA1);  vk[j+1] = mul2(vi2, kk[j+1]);
      sA2 = fma2(S[j+2], aa[j+2], sA2);  vk[j+2] = mul2(vi2, kk[j+2]);
      sA3 = fma2(S[j+3], aa[j+3], sA3);  vk[j+3] = mul2(vi2, kk[j+3]);
    }
    #pragma unroll
    for (int j = 0; j < 16; j++) vk[j] = fma2(S[j], dd[j], vk[j]);

    float2 u0 = f2unpack(sA0), u1 = f2unpack(sA1), u2 = f2unpack(sA2), u3 = f2unpack(sA3);
    float sap = ((u0.x + u0.y) + (u1.x + u1.y)) + ((u2.x + u2.y) + (u3.x + u3.y));
    float sa  = sap + __shfl_xor_sync(0xffffffffu, sap, 1);
    unsigned long long sa2 = f2pack(sa, sa);

    unsigned long long oA0=0ull, oA1=0ull, oA2=0ull, oA3=0ull;
    #pragma unroll
    for (int j = 0; j < 16; j += 4){
      S[j]   = fma2(sa2, bb[j],   vk[j]);    oA0 = fma2(S[j],   rr[j],   oA0);
      S[j+1] = fma2(sa2, bb[j+1], vk[j+1]);  oA1 = fma2(S[j+1], rr[j+1], oA1);
      S[j+2] = fma2(sa2, bb[j+2], vk[j+2]);  oA2 = fma2(S[j+2], rr[j+2], oA2);
      S[j+3] = fma2(sa2, bb[j+3], vk[j+3]);  oA3 = fma2(S[j+3], rr[j+3], oA3);
    }
    float2 w0_ = f2unpack(oA0), w1_ = f2unpack(oA1), w2_ = f2unpack(oA2), w3_ = f2unpack(oA3);
    float op = ((w0_.x + w0_.y) + (w1_.x + w1_.y)) + ((w2_.x + w2_.y) + (w3_.x + w3_.y));
    float ofull = op + __shfl_xor_sync(0xffffffffu, op, 1);
    if (half == 0) o[t*Cc + hb + row] = ofull;
  }
}

__global__ void __launch_bounds__(64) post_kernel(
    const float* __restrict__ r, const float* __restrict__ k,
    const float* __restrict__ v, const float* __restrict__ r_k,
    float* __restrict__ o)
{
  int t = blockIdx.x >> 5;
  int h = blockIdx.x & 31;
  int tid = threadIdx.x;
  int c = (h << 6) | tid;
  int idx = t*Cc + c;
  __shared__ float red[64];
  red[tid] = r[idx]*k[idx]*r_k[c];
  __syncthreads();
  #pragma unroll
  for (int s = 32; s > 0; s >>= 1){
    if (tid < s) red[tid] += red[tid + s];
    __syncthreads();
  }
  o[idx] += red[0]*v[idx];
}

__global__ void copy_vfirst(const float* __restrict__ vf, float* __restrict__ out)
{
  int i = blockIdx.x*256 + threadIdx.x;
  if (i < TC) out[i] = vf[i];
}

// ---------------- host launcher ----------------
extern "C" void kernel_launch(void* const* d_in, const int* in_sizes, int n_in,
                              void* d_out, int out_size)
{
  const float* x        = (const float*)d_in[0];
  const float* v_first  = (const float*)d_in[1];
  const float* mask     = (const float*)d_in[2];
  const float* w0       = (const float*)d_in[3];
  const float* w1       = (const float*)d_in[4];
  const float* w2       = (const float*)d_in[5];
  const float* a0       = (const float*)d_in[6];
  const float* a1       = (const float*)d_in[7];
  const float* a2       = (const float*)d_in[8];
  const float* v0       = (const float*)d_in[9];
  const float* v1       = (const float*)d_in[10];
  const float* v2       = (const float*)d_in[11];
  const float* k_k      = (const float*)d_in[12];
  const float* k_a      = (const float*)d_in[13];
  const float* r_k      = (const float*)d_in[14];
  const float* Wr       = (const float*)d_in[15];
  const float* Wk       = (const float*)d_in[16];
  const float* Wv       = (const float*)d_in[17];
  const float* Wo       = (const float*)d_in[18];
  float* outf = (float*)d_out;

  float* S = nullptr;
  cudaGetSymbolAddress((void**)&S, g_scratch);
  __nv_bfloat16* BF = nullptr;
  cudaGetSymbolAddress((void**)&BF, g_bf16);

  float* bcat = S;                       // unused float region (kept for layout)
  float* part = bcat + 524288;
  float* hcat = part + 2097152;          // unused (hcat now bf16 split)
  float* gw   = hcat + 262144;
  float* ga   = gw  + TC;
  float* gv   = ga  + TC;
  float* r    = gv  + TC;
  float* k    = r   + TC;
  float* v    = k   + TC;
  float* dec  = v   + TC;
  float* asc  = dec + TC;
  float* bsc  = asc + TC;
  float* ksc  = bsc + TC;
  float* vsc  = ksc + TC;
  float* o    = vsc + TC;

  __nv_bfloat16* xh = BF;
  __nv_bfloat16* xl = xh + TC;
  __nv_bfloat16* oh = xl + TC;
  __nv_bfloat16* ol = oh + TC;
  __nv_bfloat16* Wt = ol + TC;
  __nv_bfloat16* Wrh = Wt + 0*WSZ, *Wrl = Wt + 1*WSZ;
  __nv_bfloat16* Wkh = Wt + 2*WSZ, *Wkl = Wt + 3*WSZ;
  __nv_bfloat16* Wvh = Wt + 4*WSZ, *Wvl = Wt + 5*WSZ;
  __nv_bfloat16* Woh = Wt + 6*WSZ, *Wol = Wt + 7*WSZ;
  __nv_bfloat16* ext  = Wt + 8*WSZ;
  __nv_bfloat16* bcTh = ext;                 // [256,2048]
  __nv_bfloat16* bcTl = bcTh + 524288;
  __nv_bfloat16* w2Th = bcTl + 524288;       // [2048,128]
  __nv_bfloat16* w2Tl = w2Th + 262144;
  __nv_bfloat16* a2Th = w2Tl + 262144;       // [2048,128]
  __nv_bfloat16* a2Tl = a2Th + 262144;
  __nv_bfloat16* v2Th = a2Tl + 262144;       // [2048,64]
  __nv_bfloat16* v2Tl = v2Th + 131072;
  __nv_bfloat16* hch  = v2Tl + 131072;       // [1024,256]
  __nv_bfloat16* hcl  = hch + 262144;

  cudaFuncSetAttribute(gemm_tcg, cudaFuncAttributeMaxDynamicSharedMemorySize, GEMM_SMEM_ALLOC);

  // 0) operand prep
  tsplit<<<dim3(64,64,4), dim3(32,8)>>>(Wr, Wk, Wv, Wo, Wt);
  splitf<<<TC/256, 256>>>(x, xh, xl, TC);
  build_bcatT<<<(256*2048)/256, 256>>>(w1, a1, v1, bcTh, bcTl);
  build_m2T<<<dim3(1024,1,3), 256>>>(w2, a2, v2, w2Th, w2Tl, a2Th, a2Tl, v2Th, v2Tl);

  // 1) thin GEMM on tensor cores: part[z] = x[:, z*256:(z+1)*256] @ bcat slice (split-K 8)
  {
    dim3 grid(2, 8, 8);
    gemm_tcg<<<grid, 128, GEMM_SMEM_ALLOC>>>(
        xh, xl, 2048,
        bcTh, bcTl, bcTh, bcTl, bcTh, bcTl, 2048,
        part, part, part, 256,
        4, /*kslice=*/256, /*cslice=*/262144LL, 0, 0);
  }
  // 2) reduce partials (+ tanh on w-path) -> bf16 split hcat
  reduce_hcat<<<1024, 256>>>(part, hch, hcl);

  // 3) mid GEMMs on tensor cores
  {
    dim3 gwa(16, 8, 2);   // z=0: gw = hcat_w @ w2 ; z=1: ga = hcat_a @ a2 (K=96, 2 chunks)
    gemm_tcg<<<gwa, 128, GEMM_SMEM_ALLOC>>>(
        hch, hcl, 256,
        w2Th, w2Tl, a2Th, a2Tl, a2Th, a2Tl, 128,
        gw, ga, ga, 2048,
        2, 0, 0LL, /*acol0=*/0, /*acolz=*/96);
    dim3 gv_(16, 8, 1);   // gv = hcat_v @ v2 (K=64, 1 chunk)
    gemm_tcg<<<gv_, 128, GEMM_SMEM_ALLOC>>>(
        hch, hcl, 256,
        v2Th, v2Tl, v2Th, v2Tl, v2Th, v2Tl, 64,
        gv, gv, gv, 2048,
        1, 0, 0LL, /*acol0=*/192, 0);
  }

  // 4) big GEMMs: r,k,v = x @ {Wr,Wk,Wv}
  {
    dim3 grid(16, 8, 3);
    gemm_tcg<<<grid, 128, GEMM_SMEM_ALLOC>>>(
        xh, xl, 2048,
        Wrh, Wrl, Wkh, Wkl, Wvh, Wvl, 2048,
        r, k, v, 2048,
        32, 0, 0LL, 0, 0);
  }

  // 5) elementwise prep
  prep_kernel<<<Tt*Hh, 64>>>(k, v, gw, ga, gv, v_first, mask,
                             w0, a0, v0, k_k, k_a,
                             dec, asc, bsc, ksc, vsc);

  // 6) sequential scan (128 threads/head)
  scan_kernel<<<Hh, 128>>>(dec, r, ksc, vsc, asc, bsc, o);

  // 7) residual
  post_kernel<<<Tt*Hh, 64>>>(r, k, v, r_k, o);

  // 8) final GEMM: out = o @ Wo
  splitf<<<TC/256, 256>>>(o, oh, ol, TC);
  {
    dim3 grid(16, 8, 1);
    gemm_tcg<<<grid, 128, GEMM_SMEM_ALLOC>>>(
        oh, ol, 2048,
        Woh, Wol, Woh, Wol, Woh, Wol, 2048,
        outf, outf, outf, 2048,
        32, 0, 0LL, 0, 0);
  }

  // 9) v_first pass-through
  if (out_size >= 2*TC) {
    copy_vfirst<<<(TC + 255)/256, 256>>>(v_first, outf + TC);
  }
}